// round 12
// baseline (speedup 1.0000x reference)
#include <cuda_runtime.h>
#include <cstdint>
#include <math.h>

#define B_SLIDES 64
#define N_CELLS  20000
#define NI       64
#define H1       16
#define H2       8
#define N_OUT    2

#define TPB      128                 // 4 warps
#define CSTAGE   256                 // cells per tile (2 per thread)
#define CHUNKS   13
#define CELLS_PER_CHUNK ((N_CELLS + CHUNKS - 1) / CHUNKS)   // 1539
#define TOTAL_BLOCKS (CHUNKS * B_SLIDES)                    // 832 (<= 6*148=888, one wave)

// Staging: 256 rows x 128 bytes (one K-half per phase), XOR-swizzled 16B units
#define XS_BYTES (CSTAGE * 128)      // 32768
#define SMEM_BYTES (XS_BYTES + 512 + 32 + 32 + 160 + 64)

typedef unsigned long long ull;

// ---- FULL W1 (+b1) in constant memory ----
__constant__ ull   cW1p[NI * H1 / 2];   // W1[64][16] raw -> [64][8] fp32-pairs (4KB)
__constant__ float cb1[H1];

__device__ float        g_partials[B_SLIDES * CHUNKS * 9];
__device__ unsigned int g_count = 0;

__device__ __forceinline__ ull pack2(float lo, float hi) {
    ull r; asm("mov.b64 %0, {%1, %2};" : "=l"(r) : "f"(lo), "f"(hi)); return r;
}
__device__ __forceinline__ void unpack2(ull v, float& lo, float& hi) {
    asm("mov.b64 {%0, %1}, %2;" : "=f"(lo), "=f"(hi) : "l"(v));
}
// Packed fp32x2 FMA (sm_100+): two fp32 FMAs per instruction.
__device__ __forceinline__ ull fma2(ull a, ull b, ull c) {
    ull d; asm("fma.rn.f32x2 %0, %1, %2, %3;" : "=l"(d) : "l"(a), "l"(b), "l"(c)); return d;
}
__device__ __forceinline__ float ldcg(const float* p) {
    float v; asm("ld.global.cg.f32 %0, [%1];" : "=f"(v) : "l"(p)); return v;
}

// 128B rows: 8 x 16B chunks, chunk col ^ (row & 7) -> conflict-free
__device__ __forceinline__ uint32_t xs_off(int row, int col16) {
    return ((uint32_t)row << 7) + (((uint32_t)(col16 ^ (row & 7))) << 4);
}

// One K-half of layer 1 for this thread's two cells (tid and tid+128).
// Each LDC.128 weight load is amortized over BOTH cells.
template <int HALF>
__device__ __forceinline__ void layer1_half(const char* __restrict__ xs, int tid,
                                            ull* accA, ull* accB)
{
    #pragma unroll
    for (int i4 = 0; i4 < 8; ++i4) {
        float4 va = *(const float4*)(xs + xs_off(tid,       i4));
        float4 vb = *(const float4*)(xs + xs_off(tid + 128, i4));
        #pragma unroll
        for (int s = 0; s < 4; ++s) {
            int i = HALF * 32 + i4 * 4 + s;
            float xa = (s == 0) ? va.x : (s == 1) ? va.y : (s == 2) ? va.z : va.w;
            float xb = (s == 0) ? vb.x : (s == 1) ? vb.y : (s == 2) ? vb.z : vb.w;
            ull xa2 = pack2(xa, xa);
            ull xb2 = pack2(xb, xb);
            const ulonglong2* wr = (const ulonglong2*)&cW1p[i * 8];
            #pragma unroll
            for (int q = 0; q < 4; ++q) {
                ulonglong2 w = wr[q];          // one LDC.128 serves 2 cells
                accA[2 * q + 0] = fma2(xa2, w.x, accA[2 * q + 0]);
                accA[2 * q + 1] = fma2(xa2, w.y, accA[2 * q + 1]);
                accB[2 * q + 0] = fma2(xb2, w.x, accB[2 * q + 0]);
                accB[2 * q + 1] = fma2(xb2, w.y, accB[2 * q + 1]);
            }
        }
    }
}

// cp.async one K-half (128B per cell) of a 256-cell tile into swizzled SMEM.
__device__ __forceinline__ void stage_half(uint32_t xs_base,
                                           const float4* __restrict__ Xg,
                                           int base, int chunk_end, int half, int tid)
{
    #pragma unroll
    for (int k = 0; k < 16; ++k) {
        int f = tid + k * TPB;        // 0..2047
        int c = f >> 3;               // cell 0..255
        int o = f & 7;                // float4 slot within the 128B half-row
        int n = base + c;
        if (n > chunk_end - 1) n = chunk_end - 1;   // clamp (gated by valid later)
        uint32_t dst = xs_base + xs_off(c, o);
        const float4* src = &Xg[(size_t)n * (NI / 4) + half * 8 + o];
        asm volatile("cp.async.cg.shared.global [%0], [%1], 16;"
                     :: "r"(dst), "l"(src));
    }
    asm volatile("cp.async.commit_group;");
    asm volatile("cp.async.wait_group 0;");
}

__global__ __launch_bounds__(TPB, 6) void mlp_pool_kernel(
    const float* __restrict__ X,
    const float* __restrict__ W2, const float* __restrict__ b2,
    const float* __restrict__ Ww, const float* __restrict__ bw,
    const float* __restrict__ W4, const float* __restrict__ b4,
    float* __restrict__ out)
{
    extern __shared__ char smem[];
    char*  xs  = smem;                                    // 32KB swizzled staging
    ull*   w2q = (ull*)(smem + XS_BYTES);                 // 64 ull (W2 raw pairs)
    ull*   wwp = w2q + 64;                                // 4 ull
    float* b2s = (float*)(wwp + 4);                       // 8
    float* red = b2s + 8;                                 // 9 * 4
    __shared__ unsigned int s_last;

    const int tid   = threadIdx.x;
    const int b     = blockIdx.y;
    const int chunk = blockIdx.x;

    const uint32_t xs_base = (uint32_t)__cvta_generic_to_shared(smem);

    if (tid < 64) w2q[tid] = ((const ull*)W2)[tid];
    if (tid < 4)  wwp[tid] = ((const ull*)Ww)[tid];
    if (tid < 8)  b2s[tid] = b2[tid];
    const float bwv = __ldg(bw);

    const int start = chunk * CELLS_PER_CHUNK;
    const int end   = min(start + CELLS_PER_CHUNK, N_CELLS);

    const float4* __restrict__ Xg = (const float4*)(X + (size_t)b * N_CELLS * NI);

    float sw = 0.f;
    ull swh[4];
    #pragma unroll
    for (int k = 0; k < 4; ++k) swh[k] = pack2(0.f, 0.f);

    for (int base = start; base < end; base += CSTAGE) {
        const int nv = min(end - base, CSTAGE);

        // ---- phase 0: stage K[0:32) for 256 cells, partial layer-1 ----
        __syncthreads();                       // prev tile fully consumed
        stage_half(xs_base, Xg, base, end, 0, tid);
        __syncthreads();                       // half-0 visible to all

        ull accA[8], accB[8];
        #pragma unroll
        for (int jp = 0; jp < 8; ++jp) {
            ull bj = pack2(cb1[2 * jp], cb1[2 * jp + 1]);
            accA[jp] = bj; accB[jp] = bj;
        }
        layer1_half<0>(xs, tid, accA, accB);

        // ---- phase 1: stage K[32:64), finish layer-1 ----
        __syncthreads();                       // half-0 reads done
        stage_half(xs_base, Xg, base, end, 1, tid);
        __syncthreads();                       // half-1 visible
        layer1_half<1>(xs, tid, accA, accB);

        // ---- per-cell tails (regs + tiny read-only SMEM; no barrier needed) ----
        #pragma unroll
        for (int m = 0; m < 2; ++m) {
            const ull* acc = (m == 0) ? accA : accB;
            const bool valid = (m == 0) ? (tid < nv) : (tid + 128 < nv);

            float h1[H1];
            #pragma unroll
            for (int jp = 0; jp < 8; ++jp) {
                float lo, hi; unpack2(acc[jp], lo, hi);
                h1[2 * jp]     = fmaxf(lo, 0.f);
                h1[2 * jp + 1] = fmaxf(hi, 0.f);
            }

            ull acc2[4];
            #pragma unroll
            for (int kp = 0; kp < 4; ++kp) acc2[kp] = pack2(b2s[2 * kp], b2s[2 * kp + 1]);
            const ulonglong2* w2p = (const ulonglong2*)w2q;
            #pragma unroll
            for (int i = 0; i < H1; ++i) {
                ull hx = pack2(h1[i], h1[i]);
                ulonglong2 wa = w2p[i * 2 + 0];
                ulonglong2 wb = w2p[i * 2 + 1];
                acc2[0] = fma2(hx, wa.x, acc2[0]);
                acc2[1] = fma2(hx, wa.y, acc2[1]);
                acc2[2] = fma2(hx, wb.x, acc2[2]);
                acc2[3] = fma2(hx, wb.y, acc2[3]);
            }

            float h2[H2];
            #pragma unroll
            for (int kp = 0; kp < 4; ++kp) {
                float lo, hi; unpack2(acc2[kp], lo, hi);
                h2[2 * kp]     = fmaxf(lo, 0.f);
                h2[2 * kp + 1] = fmaxf(hi, 0.f);
            }

            ull g = pack2(bwv, 0.f);
            #pragma unroll
            for (int kp = 0; kp < 4; ++kp)
                g = fma2(pack2(h2[2 * kp], h2[2 * kp + 1]), wwp[kp], g);
            float glo, ghi; unpack2(g, glo, ghi);
            float wgt = 1.f / (1.f + __expf(-(glo + ghi)));
            if (!valid) wgt = 0.f;

            sw += wgt;
            ull wp = pack2(wgt, wgt);
            #pragma unroll
            for (int kp = 0; kp < 4; ++kp)
                swh[kp] = fma2(wp, pack2(h2[2 * kp], h2[2 * kp + 1]), swh[kp]);
        }
    }

    // ---- deterministic block reduction of 9 values (4 warps) ----
    float vals[9];
    vals[0] = sw;
    #pragma unroll
    for (int kp = 0; kp < 4; ++kp) {
        float lo, hi; unpack2(swh[kp], lo, hi);
        vals[1 + 2 * kp] = lo; vals[2 + 2 * kp] = hi;
    }
    #pragma unroll
    for (int off = 16; off > 0; off >>= 1) {
        #pragma unroll
        for (int k = 0; k < 9; ++k)
            vals[k] += __shfl_down_sync(0xffffffffu, vals[k], off);
    }
    const int lane = tid & 31, warp = tid >> 5;
    if (lane == 0) {
        #pragma unroll
        for (int k = 0; k < 9; ++k) red[k * 4 + warp] = vals[k];
    }
    __syncthreads();
    if (tid < 9) {
        float s = 0.f;
        #pragma unroll
        for (int w = 0; w < 4; ++w) s += red[tid * 4 + w];
        g_partials[((size_t)b * CHUNKS + chunk) * 9 + tid] = s;
    }

    // ---- last-block finalize (fused head; graph-replay-safe counter) ----
    __threadfence();
    __syncthreads();
    if (tid == 0) {
        unsigned int d = atomicAdd(&g_count, 1u);
        s_last = (d == TOTAL_BLOCKS - 1) ? 1u : 0u;
    }
    __syncthreads();

    if (s_last) {
        float* fs = (float*)xs;          // reuse staging buffer: [64][9]
        for (int p = tid; p < B_SLIDES * 9; p += TPB) {
            int bb = p / 9, k = p % 9;
            float s = 0.f;
            #pragma unroll
            for (int c = 0; c < CHUNKS; ++c)
                s += ldcg(&g_partials[((size_t)bb * CHUNKS + c) * 9 + k]);
            fs[bb * 9 + k] = s;
        }
        __syncthreads();
        if (tid < B_SLIDES) {
            float inv = 1.f / fs[tid * 9];
            #pragma unroll
            for (int o = 0; o < N_OUT; ++o) {
                float r = b4[o];
                #pragma unroll
                for (int k = 0; k < H2; ++k)
                    r += (fs[tid * 9 + 1 + k] * inv) * W4[k * N_OUT + o];
                out[tid * N_OUT + o] = r;
            }
        }
        if (tid == 0) atomicExch(&g_count, 0u);   // reset for next graph replay
    }
}

extern "C" void kernel_launch(void* const* d_in, const int* in_sizes, int n_in,
                              void* d_out, int out_size)
{
    (void)in_sizes; (void)n_in; (void)out_size;

    cudaMemcpyToSymbolAsync(cW1p, d_in[1], NI * H1 * sizeof(float), 0,
                            cudaMemcpyDeviceToDevice, 0);
    cudaMemcpyToSymbolAsync(cb1,  d_in[2], H1 * sizeof(float), 0,
                            cudaMemcpyDeviceToDevice, 0);

    cudaFuncSetAttribute(mlp_pool_kernel,
                         cudaFuncAttributeMaxDynamicSharedMemorySize, SMEM_BYTES);
    dim3 grid(CHUNKS, B_SLIDES);
    mlp_pool_kernel<<<grid, TPB, SMEM_BYTES>>>(
        (const float*)d_in[0],
        (const float*)d_in[3], (const float*)d_in[4],
        (const float*)d_in[5], (const float*)d_in[6],
        (const float*)d_in[7], (const float*)d_in[8],
        (float*)d_out);
}

// round 13
// speedup vs baseline: 1.7484x; 1.7484x over previous
#include <cuda_runtime.h>
#include <cstdint>
#include <math.h>

#define B_SLIDES 64
#define N_CELLS  20000
#define NI       64
#define H1       16
#define H2       8
#define N_OUT    2

#define TPB      128                 // 4 warps
#define CSTAGE   128                 // cells per tile (1 per thread)
#define CHUNKS   13
#define CELLS_PER_CHUNK ((N_CELLS + CHUNKS - 1) / CHUNKS)   // 1539
#define TOTAL_BLOCKS (CHUNKS * B_SLIDES)                    // 832 (<= 6*148=888, one wave)

// Staging buffer: 128 rows x 256 bytes, XOR-swizzled in 16B units
#define XS_BYTES (CSTAGE * 256)      // 32768
// + full W1 copy in SMEM (4KB) + W2 (512B) + tails
#define SMEM_BYTES (XS_BYTES + 4096 + 512 + 32 + 32 + 160 + 64)

typedef unsigned long long ull;

// ---- FULL W1 (+b1) in constant memory (port 1 of 2) ----
__constant__ ull   cW1p[NI * H1 / 2];   // W1[64][16] raw -> [64][8] fp32-pairs (4KB)
__constant__ float cb1[H1];

__device__ float        g_partials[B_SLIDES * CHUNKS * 9];
__device__ unsigned int g_count = 0;

__device__ __forceinline__ ull pack2(float lo, float hi) {
    ull r; asm("mov.b64 %0, {%1, %2};" : "=l"(r) : "f"(lo), "f"(hi)); return r;
}
__device__ __forceinline__ void unpack2(ull v, float& lo, float& hi) {
    asm("mov.b64 {%0, %1}, %2;" : "=f"(lo), "=f"(hi) : "l"(v));
}
// Packed fp32x2 FMA (sm_100+): two fp32 FMAs per instruction.
__device__ __forceinline__ ull fma2(ull a, ull b, ull c) {
    ull d; asm("fma.rn.f32x2 %0, %1, %2, %3;" : "=l"(d) : "l"(a), "l"(b), "l"(c)); return d;
}
__device__ __forceinline__ float ldcg(const float* p) {
    float v; asm("ld.global.cg.f32 %0, [%1];" : "=f"(v) : "l"(p)); return v;
}

// row-XOR swizzle: 16B column col within 256B row r -> col ^ (r & 7)
__device__ __forceinline__ uint32_t xs_off(int row, int col16) {
    return ((uint32_t)row << 8) + (((uint32_t)(col16 ^ (row & 7))) << 4);
}

__global__ __launch_bounds__(TPB, 6) void mlp_pool_kernel(
    const float* __restrict__ X,
    const float* __restrict__ W1,
    const float* __restrict__ W2, const float* __restrict__ b2,
    const float* __restrict__ Ww, const float* __restrict__ bw,
    const float* __restrict__ W4, const float* __restrict__ b4,
    float* __restrict__ out)
{
    extern __shared__ char smem[];
    char*  xs  = smem;                                    // 32KB swizzled staging
    ull*   w1s = (ull*)(smem + XS_BYTES);                 // 512 ull: full W1 copy
    ull*   w2q = w1s + 512;                               // 64 ull (W2 raw pairs)
    ull*   wwp = w2q + 64;                                // 4 ull
    float* b2s = (float*)(wwp + 4);                       // 8
    float* red = b2s + 8;                                 // 9 * 4
    __shared__ unsigned int s_last;

    const int tid   = threadIdx.x;
    const int b     = blockIdx.y;
    const int chunk = blockIdx.x;

    const uint32_t xs_base = (uint32_t)__cvta_generic_to_shared(smem);

    // ---- W1 full copy + small tail weights -> SMEM ----
    {
        const ull* W1q = (const ull*)W1;
        #pragma unroll
        for (int k = 0; k < 4; ++k) w1s[tid + k * TPB] = W1q[tid + k * TPB];
    }
    if (tid < 64) w2q[tid] = ((const ull*)W2)[tid];
    if (tid < 4)  wwp[tid] = ((const ull*)Ww)[tid];
    if (tid < 8)  b2s[tid] = b2[tid];
    const float bwv = __ldg(bw);

    const int start = chunk * CELLS_PER_CHUNK;
    const int end   = min(start + CELLS_PER_CHUNK, N_CELLS);

    const float4* __restrict__ Xg = (const float4*)(X + (size_t)b * N_CELLS * NI);

    float sw = 0.f;
    ull swh[4];
    #pragma unroll
    for (int k = 0; k < 4; ++k) swh[k] = pack2(0.f, 0.f);

    for (int base = start; base < end; base += CSTAGE) {
        __syncthreads();                     // buffer consumed by all (and smem init)

        // ---- cp.async stage: 128 cells x 64 floats -> swizzled SMEM ----
        #pragma unroll
        for (int k = 0; k < 16; ++k) {
            int f = tid + k * TPB;            // 0..2047
            int c = f >> 4;                   // cell 0..127
            int o = f & 15;                   // float4 slot
            int n = base + c;
            if (n > end - 1) n = end - 1;     // clamp (gated by valid below)
            uint32_t dst = xs_base + xs_off(c, o);
            const float4* src = &Xg[(size_t)n * (NI / 4) + o];
            asm volatile("cp.async.cg.shared.global [%0], [%1], 16;"
                         :: "r"(dst), "l"(src));
        }
        asm volatile("cp.async.commit_group;");
        asm volatile("cp.async.wait_group 0;");
        __syncthreads();

        const int nv = min(end - base, CSTAGE);
        const bool valid = (tid < nv);

        // ---- layer 1: 64 -> 16; weights split across const + SMEM ports ----
        ull acc[8];
        #pragma unroll
        for (int jp = 0; jp < 8; ++jp)
            acc[jp] = pack2(cb1[2 * jp], cb1[2 * jp + 1]);

        #pragma unroll 4
        for (int i4 = 0; i4 < 16; ++i4) {
            float4 xv = *(const float4*)(xs + xs_off(tid, i4));
            #pragma unroll
            for (int s = 0; s < 4; ++s) {
                int i = i4 * 4 + s;
                float xc = (s == 0) ? xv.x : (s == 1) ? xv.y : (s == 2) ? xv.z : xv.w;
                ull x2 = pack2(xc, xc);
                // j 0..7 from the constant port (LDC.128 x2)
                const ulonglong2* wrc = (const ulonglong2*)&cW1p[i * 8];
                // j 8..15 from SMEM broadcast (LDS.128 x2, different pipe)
                const ulonglong2* wrs = (const ulonglong2*)&w1s[i * 8 + 4];
                ulonglong2 wa = wrc[0], wb = wrc[1];
                ulonglong2 wc = wrs[0], wd = wrs[1];
                acc[0] = fma2(x2, wa.x, acc[0]);
                acc[1] = fma2(x2, wa.y, acc[1]);
                acc[2] = fma2(x2, wb.x, acc[2]);
                acc[3] = fma2(x2, wb.y, acc[3]);
                acc[4] = fma2(x2, wc.x, acc[4]);
                acc[5] = fma2(x2, wc.y, acc[5]);
                acc[6] = fma2(x2, wd.x, acc[6]);
                acc[7] = fma2(x2, wd.y, acc[7]);
            }
        }

        // ---- per-cell tail: relu -> layer2 -> relu -> gate -> accumulate ----
        float h1[H1];
        #pragma unroll
        for (int jp = 0; jp < 8; ++jp) {
            float lo, hi; unpack2(acc[jp], lo, hi);
            h1[2 * jp]     = fmaxf(lo, 0.f);
            h1[2 * jp + 1] = fmaxf(hi, 0.f);
        }

        ull acc2[4];
        #pragma unroll
        for (int kp = 0; kp < 4; ++kp) acc2[kp] = pack2(b2s[2 * kp], b2s[2 * kp + 1]);
        const ulonglong2* w2p = (const ulonglong2*)w2q;
        #pragma unroll
        for (int i = 0; i < H1; ++i) {
            ull hx = pack2(h1[i], h1[i]);
            ulonglong2 wa = w2p[i * 2 + 0];
            ulonglong2 wb = w2p[i * 2 + 1];
            acc2[0] = fma2(hx, wa.x, acc2[0]);
            acc2[1] = fma2(hx, wa.y, acc2[1]);
            acc2[2] = fma2(hx, wb.x, acc2[2]);
            acc2[3] = fma2(hx, wb.y, acc2[3]);
        }

        float h2[H2];
        #pragma unroll
        for (int kp = 0; kp < 4; ++kp) {
            float lo, hi; unpack2(acc2[kp], lo, hi);
            h2[2 * kp]     = fmaxf(lo, 0.f);
            h2[2 * kp + 1] = fmaxf(hi, 0.f);
        }

        ull g = pack2(bwv, 0.f);
        #pragma unroll
        for (int kp = 0; kp < 4; ++kp)
            g = fma2(pack2(h2[2 * kp], h2[2 * kp + 1]), wwp[kp], g);
        float glo, ghi; unpack2(g, glo, ghi);
        float wgt = 1.f / (1.f + __expf(-(glo + ghi)));
        if (!valid) wgt = 0.f;

        sw += wgt;
        ull wp = pack2(wgt, wgt);
        #pragma unroll
        for (int kp = 0; kp < 4; ++kp)
            swh[kp] = fma2(wp, pack2(h2[2 * kp], h2[2 * kp + 1]), swh[kp]);
    }

    // ---- deterministic block reduction of 9 values (4 warps) ----
    float vals[9];
    vals[0] = sw;
    #pragma unroll
    for (int kp = 0; kp < 4; ++kp) {
        float lo, hi; unpack2(swh[kp], lo, hi);
        vals[1 + 2 * kp] = lo; vals[2 + 2 * kp] = hi;
    }
    #pragma unroll
    for (int off = 16; off > 0; off >>= 1) {
        #pragma unroll
        for (int k = 0; k < 9; ++k)
            vals[k] += __shfl_down_sync(0xffffffffu, vals[k], off);
    }
    const int lane = tid & 31, warp = tid >> 5;
    if (lane == 0) {
        #pragma unroll
        for (int k = 0; k < 9; ++k) red[k * 4 + warp] = vals[k];
    }
    __syncthreads();
    if (tid < 9) {
        float s = 0.f;
        #pragma unroll
        for (int w = 0; w < 4; ++w) s += red[tid * 4 + w];
        g_partials[((size_t)b * CHUNKS + chunk) * 9 + tid] = s;
    }

    // ---- last-block finalize (fused head; graph-replay-safe counter) ----
    __threadfence();
    __syncthreads();
    if (tid == 0) {
        unsigned int d = atomicAdd(&g_count, 1u);
        s_last = (d == TOTAL_BLOCKS - 1) ? 1u : 0u;
    }
    __syncthreads();

    if (s_last) {
        float* fs = (float*)xs;          // reuse staging buffer: [64][9]
        for (int p = tid; p < B_SLIDES * 9; p += TPB) {
            int bb = p / 9, k = p % 9;
            float s = 0.f;
            #pragma unroll
            for (int c = 0; c < CHUNKS; ++c)
                s += ldcg(&g_partials[((size_t)bb * CHUNKS + c) * 9 + k]);
            fs[bb * 9 + k] = s;
        }
        __syncthreads();
        if (tid < B_SLIDES) {
            float inv = 1.f / fs[tid * 9];
            #pragma unroll
            for (int o = 0; o < N_OUT; ++o) {
                float r = b4[o];
                #pragma unroll
                for (int k = 0; k < H2; ++k)
                    r += (fs[tid * 9 + 1 + k] * inv) * W4[k * N_OUT + o];
                out[tid * N_OUT + o] = r;
            }
        }
        if (tid == 0) atomicExch(&g_count, 0u);   // reset for next graph replay
    }
}

extern "C" void kernel_launch(void* const* d_in, const int* in_sizes, int n_in,
                              void* d_out, int out_size)
{
    (void)in_sizes; (void)n_in; (void)out_size;

    // Full W1 + b1 into constant memory (raw D2D copies, graph-capturable).
    cudaMemcpyToSymbolAsync(cW1p, d_in[1], NI * H1 * sizeof(float), 0,
                            cudaMemcpyDeviceToDevice, 0);
    cudaMemcpyToSymbolAsync(cb1,  d_in[2], H1 * sizeof(float), 0,
                            cudaMemcpyDeviceToDevice, 0);

    cudaFuncSetAttribute(mlp_pool_kernel,
                         cudaFuncAttributeMaxDynamicSharedMemorySize, SMEM_BYTES);
    dim3 grid(CHUNKS, B_SLIDES);
    mlp_pool_kernel<<<grid, TPB, SMEM_BYTES>>>(
        (const float*)d_in[0],
        (const float*)d_in[1],
        (const float*)d_in[3], (const float*)d_in[4],
        (const float*)d_in[5], (const float*)d_in[6],
        (const float*)d_in[7], (const float*)d_in[8],
        (float*)d_out);
}